// round 16
// baseline (speedup 1.0000x reference)
#include <cuda_runtime.h>
#include <math.h>

// FFM forward, slot-major fused gather + PDL combine.
//  K1 phases (block ranges => temporal phases, L2-friendly working sets):
//    [0, BPS)            field-3, ALL 5 slots per warp (32MB working set) +
//                        feat2/feat3 (L tables are small, coexist in L2)
//    [BPS, 6*BPS)        field-2 slots 0..4 (32MB subtable/slot; adjacent-phase
//                        blur = 64MB still fits the 126MB L2)
//  K2 (combine): PDL-launched; runs K1-independent 1-step gathers first, then
//  grid-sync, scratch readback, pair dots, sigmoid.

#define WPB   8
#define BATCH 16384
#define BPS   (BATCH / WPB)   // 2048 blocks per phase

__device__ __align__(16) float g_v2[BATCH * 80];   // 5 slots x 16
__device__ __align__(16) float g_v3[BATCH * 80];
__device__ float g_feat2[BATCH];
__device__ float g_feat3[BATCH];

__constant__ int c_pair_i[15] = {0,0,0,0,0,1,1,1,1,2,2,2,3,3,4};
__constant__ int c_pair_j[15] = {1,2,3,4,5,2,3,4,5,3,4,5,4,5,5};

// ---- field-2 single-slot gather: one warp = one (batch, slot) ----
__device__ __forceinline__ void f2_slot_gather(
    const int* __restrict__ x2, const float* __restrict__ E2,
    int slot, int b, int lane)
{
    const int dg    = lane >> 2;
    const int chunk = lane & 3;

    const int ia = __ldg(x2 + (size_t)b * 50 + lane);
    const int ib = (lane < 18) ? __ldg(x2 + (size_t)b * 50 + 32 + lane) : 0;

    const float* base = E2 + (size_t)slot * 500000 * 16 + chunk * 4;
    float4 acc = make_float4(0.f, 0.f, 0.f, 0.f);

#pragma unroll
    for (int t = 0; t < 7; ++t) {           // ceil(50/8)=7
        const int d = t * 8 + dg;
        const int idx = (d < 32) ? __shfl_sync(0xffffffffu, ia, d)
                                 : __shfl_sync(0xffffffffu, ib, d - 32);
        if (d < 50) {
            const float4 e = __ldg((const float4*)(base + (size_t)idx * 16));
            acc.x += e.x; acc.y += e.y; acc.z += e.z; acc.w += e.w;
        }
    }
#pragma unroll
    for (int off = 4; off <= 16; off <<= 1) {
        acc.x += __shfl_xor_sync(0xffffffffu, acc.x, off);
        acc.y += __shfl_xor_sync(0xffffffffu, acc.y, off);
        acc.z += __shfl_xor_sync(0xffffffffu, acc.z, off);
        acc.w += __shfl_xor_sync(0xffffffffu, acc.w, off);
    }
    if (lane < 4) {
        float4 r = make_float4(acc.x * 0.02f, acc.y * 0.02f, acc.z * 0.02f, acc.w * 0.02f);
        ((float4*)(g_v2 + (size_t)b * 80 + slot * 16))[lane] = r;
    }
}

// ---- field-3 all-slot gather + feat2/feat3: one warp = one batch ----
__device__ __forceinline__ void f3_all_slots(
    const int* __restrict__ x3, const float* __restrict__ E3,
    const float* __restrict__ L3,
    const int* __restrict__ x2, const float* __restrict__ L2,
    int b, int lane)
{
    const int dg    = lane >> 2;
    const int chunk = lane & 3;

    const int i3  = (lane < 20) ? __ldg(x3 + (size_t)b * 20 + lane) : 0;
    const int i2a = __ldg(x2 + (size_t)b * 50 + lane);
    const int i2b = (lane < 18) ? __ldg(x2 + (size_t)b * 50 + 32 + lane) : 0;

    // feats (L tables tiny, L2-resident)
    float p3 = (lane < 20) ? __ldg(L3 + i3) : 0.f;
    float p2 = __ldg(L2 + i2a) + ((lane < 18) ? __ldg(L2 + i2b) : 0.f);

#pragma unroll
    for (int slot = 0; slot < 5; ++slot) {
        const float* base = E3 + (size_t)slot * 100000 * 16 + chunk * 4;
        float4 acc = make_float4(0.f, 0.f, 0.f, 0.f);
#pragma unroll
        for (int t = 0; t < 3; ++t) {        // ceil(20/8)=3
            const int d = t * 8 + dg;
            const int idx = __shfl_sync(0xffffffffu, i3, d < 20 ? d : 0);
            if (d < 20) {
                const float4 e = __ldg((const float4*)(base + (size_t)idx * 16));
                acc.x += e.x; acc.y += e.y; acc.z += e.z; acc.w += e.w;
            }
        }
#pragma unroll
        for (int off = 4; off <= 16; off <<= 1) {
            acc.x += __shfl_xor_sync(0xffffffffu, acc.x, off);
            acc.y += __shfl_xor_sync(0xffffffffu, acc.y, off);
            acc.z += __shfl_xor_sync(0xffffffffu, acc.z, off);
            acc.w += __shfl_xor_sync(0xffffffffu, acc.w, off);
        }
        if (lane < 4) {
            float4 r = make_float4(acc.x * 0.05f, acc.y * 0.05f, acc.z * 0.05f, acc.w * 0.05f);
            ((float4*)(g_v3 + (size_t)b * 80 + slot * 16))[lane] = r;
        }
    }

#pragma unroll
    for (int off = 16; off; off >>= 1) {
        p2 += __shfl_xor_sync(0xffffffffu, p2, off);
        p3 += __shfl_xor_sync(0xffffffffu, p3, off);
    }
    if (lane == 0) { g_feat2[b] = p2 * 0.02f; g_feat3[b] = p3 * 0.05f; }
}

extern "C" __global__ void __launch_bounds__(WPB * 32)
ffm_gather_fused(const int* __restrict__ x2, const float* __restrict__ E2,
                 const float* __restrict__ L2,
                 const int* __restrict__ x3, const float* __restrict__ E3,
                 const float* __restrict__ L3)
{
    const int warp = threadIdx.x >> 5;
    const int lane = threadIdx.x & 31;

    int bid = blockIdx.x;
    if (bid < BPS) {
        f3_all_slots(x3, E3, L3, x2, L2, bid * WPB + warp, lane);
    } else {
        bid -= BPS;
        const int slot = bid / BPS;
        const int bx   = bid - slot * BPS;
        f2_slot_gather(x2, E2, slot, bx * WPB + warp, lane);
    }

#if __CUDA_ARCH__ >= 900
    cudaTriggerProgrammaticLaunchCompletion();
#endif
}

// ---------------- K2: combine (PDL-overlapped, no L/index gathers) ----------
extern "C" __global__ void __launch_bounds__(WPB * 32)
ffm_combine(const int* __restrict__ x0, const int* __restrict__ x1,
            const int* __restrict__ x4, const int* __restrict__ x5,
            const float* __restrict__ E0, const float* __restrict__ E1,
            const float* __restrict__ E4, const float* __restrict__ E5,
            const float* __restrict__ L0, const float* __restrict__ L1,
            const float* __restrict__ L4, const float* __restrict__ L5,
            const float* __restrict__ Wd, const float* __restrict__ bd,
            float* __restrict__ out)
{
    __shared__ __align__(16) float sv[WPB][6 * 80];
    __shared__ float sfeat[WPB][8];

    const int warp = threadIdx.x >> 5;
    const int lane = threadIdx.x & 31;
    const int b = blockIdx.x * WPB + warp;
    if (b >= BATCH) return;

    float* v    = sv[warp];
    float* feat = sfeat[warp];

    const int slot  = lane >> 2;
    const int chunk = lane & 3;

    // ======== Phase A: independent of K1 (overlaps K1 drain via PDL) ========
    const int idx0 = __ldg(x0 + b);
    const int idx1 = __ldg(x1 + b);
    const int idx4 = __ldg(x4 + b);
    const int idx5 = __ldg(x5 + b);

    if (lane < 20) {
        const float4 e0 = __ldg((const float4*)(E0 + ((size_t)slot * 1000000 + idx0) * 16) + chunk);
        const float4 e1 = __ldg((const float4*)(E1 + ((size_t)slot * 500000  + idx1) * 16) + chunk);
        const float4 e4 = __ldg((const float4*)(E4 + ((size_t)slot * 10000   + idx4) * 16) + chunk);
        const float4 e5 = __ldg((const float4*)(E5 + ((size_t)slot * 1000    + idx5) * 16) + chunk);
        ((float4*)(v + 0 * 80))[lane] = e0;
        ((float4*)(v + 1 * 80))[lane] = e1;
        ((float4*)(v + 4 * 80))[lane] = e4;
        ((float4*)(v + 5 * 80))[lane] = e5;
    } else if (lane == 20) feat[0] = __ldg(L0 + idx0);
    else if (lane == 21)   feat[1] = __ldg(L1 + idx1);
    else if (lane == 22)   feat[4] = __ldg(L4 + idx4);
    else if (lane == 23)   feat[5] = __ldg(L5 + idx5);

    // ======== Phase B: wait for K1, consume scratch ========
#if __CUDA_ARCH__ >= 900
    cudaGridDependencySynchronize();
#endif

    if (lane < 20) {
        ((float4*)(v + 2 * 80))[lane] = ((const float4*)(g_v2 + (size_t)b * 80))[lane];
        ((float4*)(v + 3 * 80))[lane] = ((const float4*)(g_v3 + (size_t)b * 80))[lane];
    } else if (lane == 24) feat[2] = g_feat2[b];
    else if (lane == 25)   feat[3] = g_feat3[b];
    __syncwarp();

    // pair interactions: 15 pairs x 4 chunks = 60 items
    float partial = 0.f;
#pragma unroll
    for (int r = 0; r < 2; ++r) {
        const int item = lane + r * 32;
        if (item < 60) {
            const int t = item >> 2;
            const int c = item & 3;
            const int i = c_pair_i[t];
            const int j = c_pair_j[t];
            const float4 a  = *(const float4*)(v + i * 80 + (j - 1) * 16 + c * 4);
            const float4 bb = *(const float4*)(v + j * 80 +  i      * 16 + c * 4);
            partial += a.x * bb.x + a.y * bb.y + a.z * bb.z + a.w * bb.w;
        }
    }
#pragma unroll
    for (int off = 16; off; off >>= 1)
        partial += __shfl_xor_sync(0xffffffffu, partial, off);

    if (lane == 0) {
        float lin = __ldg(bd);
#pragma unroll
        for (int i = 0; i < 6; ++i) lin += feat[i] * __ldg(Wd + i);
        lin = fmaxf(lin, 0.f);
        out[b] = 1.0f / (1.0f + expf(-(lin + partial)));
    }
}

extern "C" void kernel_launch(void* const* d_in, const int* in_sizes, int n_in,
                              void* d_out, int out_size)
{
    const int* xs[6];
    for (int i = 0; i < 6; ++i) xs[i] = (const int*)d_in[i];

    // Classify E/L by element count (robust to input ordering):
    // E_i has 80*DIM_i elements, L_i has DIM_i. Disjoint size sets.
    const float* E[6] = {0,0,0,0,0,0};
    const float* L[6] = {0,0,0,0,0,0};
    const float* Wd = 0;
    const float* bd = 0;
    int ei = 0, li = 0;
    for (int k = 6; k < n_in; ++k) {
        const long long sz = (long long)in_sizes[k];
        const float* p = (const float*)d_in[k];
        if (sz == 80000000LL || sz == 40000000LL || sz == 8000000LL ||
            sz == 800000LL   || sz == 80000LL) {
            if (ei < 6) E[ei++] = p;
        } else if (sz == 1000000LL || sz == 500000LL || sz == 100000LL ||
                   sz == 10000LL   || sz == 1000LL) {
            if (li < 6) L[li++] = p;
        } else if (sz == 6LL) {
            Wd = p;
        } else if (sz == 1LL) {
            bd = p;
        }
    }

    float* out = (float*)d_out;

    // K1: f3 all-slots phase (+feats), then f2 slot phases
    ffm_gather_fused<<<BPS * 6, WPB * 32>>>(xs[2], E[2], L[2],
                                            xs[3], E[3], L[3]);

    // K2: combine with PDL (overlaps K1 drain; correct under fallback too)
    {
        cudaLaunchConfig_t cfg = {};
        cfg.gridDim  = dim3(BPS, 1, 1);
        cfg.blockDim = dim3(WPB * 32, 1, 1);
        cfg.dynamicSmemBytes = 0;
        cfg.stream = 0;
        cudaLaunchAttribute attrs[1];
        attrs[0].id = cudaLaunchAttributeProgrammaticStreamSerialization;
        attrs[0].val.programmaticStreamSerializationAllowed = 1;
        cfg.attrs = attrs;
        cfg.numAttrs = 1;
        cudaError_t err = cudaLaunchKernelEx(&cfg, ffm_combine,
            xs[0], xs[1], xs[4], xs[5],
            E[0], E[1], E[4], E[5],
            L[0], L[1], L[4], L[5],
            Wd, bd, out);
        if (err != cudaSuccess) {
            ffm_combine<<<BPS, WPB * 32>>>(
                xs[0], xs[1], xs[4], xs[5],
                E[0], E[1], E[4], E[5],
                L[0], L[1], L[4], L[5],
                Wd, bd, out);
        }
    }
}